// round 1
// baseline (speedup 1.0000x reference)
#include <cuda_runtime.h>
#include <math.h>

#define Dm 128
#define TILE 128
#define TS 129            // padded smem row stride (floats)
#define NROWS 8192        // B*T
#define NCH 64            // total chunks (B*T/128)
#define CPB 32            // chunks per batch
#define LN_EPS 1e-5f
#define ATT_EPS 1e-6f

// ---- scratch (device globals; no allocation allowed) ----
__device__ float g_Qp[NROWS * Dm];
__device__ float g_Kp[NROWS * Dm];
__device__ float g_Vg[NROWS * Dm];
__device__ float g_U [NCH * Dm * Dm];
__device__ float g_uv[NCH * Dm];
__device__ float g_S [NCH * Dm * Dm];   // exclusive prefix of U
__device__ float g_sv[NCH * Dm];        // exclusive prefix of u

// ---- helpers ----
__device__ __forceinline__ void load_tile_g2s(const float* __restrict__ g, float* __restrict__ s) {
    // 128x128 fp32 tile, global row-major -> smem with TS stride
    int tid = threadIdx.x;
    const float4* g4 = (const float4*)g;
#pragma unroll
    for (int i = 0; i < 16; i++) {
        int idx = tid + i * 256;
        float4 v = g4[idx];
        int e = idx * 4;
        int r = e >> 7, c = e & 127;
        float* p = s + r * TS + c;
        p[0] = v.x; p[1] = v.y; p[2] = v.z; p[3] = v.w;
    }
}

__device__ __forceinline__ void mm_zero(float acc[8][8]) {
#pragma unroll
    for (int i = 0; i < 8; i++)
#pragma unroll
        for (int j = 0; j < 8; j++) acc[i][j] = 0.f;
}

// acc += A[tr+i][k] * B[k][tc+j]
__device__ __forceinline__ void mm_rowrow(const float* __restrict__ A, const float* __restrict__ B,
                                          float acc[8][8], int tr, int tc) {
#pragma unroll 4
    for (int k = 0; k < 128; k++) {
        float a[8], b[8];
#pragma unroll
        for (int i = 0; i < 8; i++) a[i] = A[(tr + i) * TS + k];
#pragma unroll
        for (int j = 0; j < 8; j++) b[j] = B[k * TS + tc + j];
#pragma unroll
        for (int i = 0; i < 8; i++)
#pragma unroll
            for (int j = 0; j < 8; j++) acc[i][j] = fmaf(a[i], b[j], acc[i][j]);
    }
}

// acc += A[tr+i][k] * B[tc+j][k]   (B transposed)
__device__ __forceinline__ void mm_rowcol(const float* __restrict__ A, const float* __restrict__ B,
                                          float acc[8][8], int tr, int tc) {
#pragma unroll 4
    for (int k = 0; k < 128; k++) {
        float a[8], b[8];
#pragma unroll
        for (int i = 0; i < 8; i++) a[i] = A[(tr + i) * TS + k];
#pragma unroll
        for (int j = 0; j < 8; j++) b[j] = B[(tc + j) * TS + k];
#pragma unroll
        for (int i = 0; i < 8; i++)
#pragma unroll
            for (int j = 0; j < 8; j++) acc[i][j] = fmaf(a[i], b[j], acc[i][j]);
    }
}

// acc += A[k][tr+i] * B[k][tc+j]   (A transposed)
__device__ __forceinline__ void mm_colrow(const float* __restrict__ A, const float* __restrict__ B,
                                          float acc[8][8], int tr, int tc) {
#pragma unroll 4
    for (int k = 0; k < 128; k++) {
        float a[8], b[8];
#pragma unroll
        for (int i = 0; i < 8; i++) a[i] = A[k * TS + tr + i];
#pragma unroll
        for (int j = 0; j < 8; j++) b[j] = B[k * TS + tc + j];
#pragma unroll
        for (int i = 0; i < 8; i++)
#pragma unroll
            for (int j = 0; j < 8; j++) acc[i][j] = fmaf(a[i], b[j], acc[i][j]);
    }
}

__device__ __forceinline__ float phi_f(float x) {   // elu(x)+1
    return x > 0.f ? x + 1.f : expf(x);
}
__device__ __forceinline__ float sigmoid_f(float x) {
    return 1.f / (1.f + expf(-x));
}

// ---- kernel A: LN1 + Q/K/V/G projections + activations ----
__global__ void __launch_bounds__(256) k_proj(
    const float* __restrict__ tokens, const float* __restrict__ Wq,
    const float* __restrict__ Wk, const float* __restrict__ Wv,
    const float* __restrict__ Wg, const float* __restrict__ bg,
    const float* __restrict__ g1, const float* __restrict__ b1)
{
    extern __shared__ float sm[];
    float* x_s = sm;
    float* w_s = sm + TILE * TS;
    float* v_s = sm + 2 * TILE * TS;
    int tid = threadIdx.x, lane = tid & 31, warp = tid >> 5;
    int row0 = blockIdx.x * TILE;

    // LayerNorm rows into x_s (one warp per row)
    for (int r = warp; r < TILE; r += 8) {
        float4 v = ((const float4*)(tokens + (size_t)(row0 + r) * Dm))[lane];
        float s = v.x + v.y + v.z + v.w;
        float ss = v.x * v.x + v.y * v.y + v.z * v.z + v.w * v.w;
        for (int o = 16; o; o >>= 1) {
            s  += __shfl_xor_sync(0xffffffffu, s,  o);
            ss += __shfl_xor_sync(0xffffffffu, ss, o);
        }
        float mu = s * (1.f / 128.f);
        float inv = rsqrtf(ss * (1.f / 128.f) - mu * mu + LN_EPS);
        int c = lane * 4;
        x_s[r * TS + c + 0] = (v.x - mu) * inv * g1[c + 0] + b1[c + 0];
        x_s[r * TS + c + 1] = (v.y - mu) * inv * g1[c + 1] + b1[c + 1];
        x_s[r * TS + c + 2] = (v.z - mu) * inv * g1[c + 2] + b1[c + 2];
        x_s[r * TS + c + 3] = (v.w - mu) * inv * g1[c + 3] + b1[c + 3];
    }
    __syncthreads();

    int tr = (tid >> 4) * 8, tc = (tid & 15) * 8;
    float acc[8][8];

    // Q -> phi -> g_Qp
    load_tile_g2s(Wq, w_s);
    __syncthreads();
    mm_zero(acc);
    mm_rowrow(x_s, w_s, acc, tr, tc);
#pragma unroll
    for (int i = 0; i < 8; i++)
#pragma unroll
        for (int j = 0; j < 8; j++)
            g_Qp[(size_t)(row0 + tr + i) * Dm + tc + j] = phi_f(acc[i][j]);
    __syncthreads();

    // K -> phi -> g_Kp
    load_tile_g2s(Wk, w_s);
    __syncthreads();
    mm_zero(acc);
    mm_rowrow(x_s, w_s, acc, tr, tc);
#pragma unroll
    for (int i = 0; i < 8; i++)
#pragma unroll
        for (int j = 0; j < 8; j++)
            g_Kp[(size_t)(row0 + tr + i) * Dm + tc + j] = phi_f(acc[i][j]);
    __syncthreads();

    // V -> keep in v_s
    load_tile_g2s(Wv, w_s);
    __syncthreads();
    mm_zero(acc);
    mm_rowrow(x_s, w_s, acc, tr, tc);
#pragma unroll
    for (int i = 0; i < 8; i++)
#pragma unroll
        for (int j = 0; j < 8; j++)
            v_s[(tr + i) * TS + tc + j] = acc[i][j];
    __syncthreads();

    // G -> Vg = V * sigmoid(G + bg) -> g_Vg
    load_tile_g2s(Wg, w_s);
    __syncthreads();
    mm_zero(acc);
    mm_rowrow(x_s, w_s, acc, tr, tc);
#pragma unroll
    for (int i = 0; i < 8; i++)
#pragma unroll
        for (int j = 0; j < 8; j++) {
            float gate = sigmoid_f(acc[i][j] + bg[tc + j]);
            g_Vg[(size_t)(row0 + tr + i) * Dm + tc + j] = v_s[(tr + i) * TS + tc + j] * gate;
        }
}

// ---- kernel B: per-chunk U = Kp^T Vg, u = colsum(Kp) ----
__global__ void __launch_bounds__(256) k_chunkU() {
    extern __shared__ float sm[];
    float* k_s = sm;
    float* v_s = sm + TILE * TS;
    int ci = blockIdx.x;
    int row0 = ci * TILE;
    load_tile_g2s(g_Kp + (size_t)row0 * Dm, k_s);
    load_tile_g2s(g_Vg + (size_t)row0 * Dm, v_s);
    __syncthreads();
    int tid = threadIdx.x;
    int tr = (tid >> 4) * 8, tc = (tid & 15) * 8;
    float acc[8][8];
    mm_zero(acc);
    mm_colrow(k_s, v_s, acc, tr, tc);
#pragma unroll
    for (int i = 0; i < 8; i++)
#pragma unroll
        for (int j = 0; j < 8; j++)
            g_U[(size_t)ci * (Dm * Dm) + (tr + i) * Dm + tc + j] = acc[i][j];
    if (tid < 128) {
        float s = 0.f;
        for (int t = 0; t < 128; t++) s += k_s[t * TS + tid];
        g_uv[ci * Dm + tid] = s;
    }
}

// ---- kernel C: exclusive prefix over chunks (per batch) ----
__global__ void k_prefix() {
    int b = blockIdx.y;
    int e = blockIdx.x * blockDim.x + threadIdx.x;
    if (e < Dm * Dm) {
        float acc = 0.f;
        for (int c = 0; c < CPB; c++) {
            int ci = b * CPB + c;
            g_S[(size_t)ci * (Dm * Dm) + e] = acc;
            acc += g_U[(size_t)ci * (Dm * Dm) + e];
        }
    } else if (e < Dm * Dm + Dm) {
        int h = e - Dm * Dm;
        float acc = 0.f;
        for (int c = 0; c < CPB; c++) {
            int ci = b * CPB + c;
            g_sv[ci * Dm + h] = acc;
            acc += g_uv[ci * Dm + h];
        }
    }
}

// ---- kernel D: intra+inter attention, Wo, residual, LN2 ----
__global__ void __launch_bounds__(256) k_attn(
    const float* __restrict__ tokens, const float* __restrict__ Wo,
    const float* __restrict__ g2, const float* __restrict__ b2,
    float* __restrict__ out)
{
    extern __shared__ float sm[];
    float* bufA = sm;                       // Qp (persists), later out tile
    float* bufB = sm + TILE * TS;           // Kp -> masked A -> attn
    float* bufC = sm + 2 * TILE * TS;       // Vg -> Sprev -> Wo
    float* sprev_s = sm + 3 * TILE * TS;    // 128
    float* denom_s = sprev_s + 128;         // 128
    int tid = threadIdx.x, lane = tid & 31, warp = tid >> 5;
    int ci = blockIdx.x;
    int row0 = ci * TILE;

    load_tile_g2s(g_Qp + (size_t)row0 * Dm, bufA);
    load_tile_g2s(g_Kp + (size_t)row0 * Dm, bufB);
    if (tid < 128) sprev_s[tid] = g_sv[ci * Dm + tid];
    __syncthreads();

    int tr = (tid >> 4) * 8, tc = (tid & 15) * 8;
    float acc[8][8];

    // A = Qp Kp^T, causal mask (diag inclusive)
    mm_zero(acc);
    mm_rowcol(bufA, bufB, acc, tr, tc);
#pragma unroll
    for (int i = 0; i < 8; i++)
#pragma unroll
        for (int j = 0; j < 8; j++)
            if (tc + j > tr + i) acc[i][j] = 0.f;
    __syncthreads();
#pragma unroll
    for (int i = 0; i < 8; i++)
#pragma unroll
        for (int j = 0; j < 8; j++)
            bufB[(tr + i) * TS + tc + j] = acc[i][j];
    __syncthreads();

    // Vg tile into bufC while computing denom from bufA/bufB
    load_tile_g2s(g_Vg + (size_t)row0 * Dm, bufC);
    for (int r = warp; r < 128; r += 8) {
        float s = 0.f;
#pragma unroll
        for (int q = 0; q < 4; q++) {
            int c = lane + q * 32;
            s += bufB[r * TS + c] + bufA[r * TS + c] * sprev_s[c];
        }
        for (int o = 16; o; o >>= 1) s += __shfl_xor_sync(0xffffffffu, s, o);
        if (lane == 0) denom_s[r] = fmaxf(s, ATT_EPS);
    }
    __syncthreads();

    // intra = A_masked @ Vg
    mm_zero(acc);
    mm_rowrow(bufB, bufC, acc, tr, tc);
    __syncthreads();
    // inter += Qp @ Sprev
    load_tile_g2s(g_S + (size_t)ci * (Dm * Dm), bufC);
    __syncthreads();
    mm_rowrow(bufA, bufC, acc, tr, tc);

    // attn = num / denom  -> bufB
#pragma unroll
    for (int i = 0; i < 8; i++) {
        float inv = 1.f / denom_s[tr + i];
#pragma unroll
        for (int j = 0; j < 8; j++)
            bufB[(tr + i) * TS + tc + j] = acc[i][j] * inv;
    }
    __syncthreads();

    // out_pre = tokens + 0.1 * attn @ Wo  -> bufA
    load_tile_g2s(Wo, bufC);
    __syncthreads();
    mm_zero(acc);
    mm_rowrow(bufB, bufC, acc, tr, tc);
#pragma unroll
    for (int i = 0; i < 8; i++)
#pragma unroll
        for (int j = 0; j < 8; j++)
            bufA[(tr + i) * TS + tc + j] =
                tokens[(size_t)(row0 + tr + i) * Dm + tc + j] + 0.1f * acc[i][j];
    __syncthreads();

    // LN2 -> out
    for (int r = warp; r < 128; r += 8) {
        int c = lane * 4;
        float v0 = bufA[r * TS + c + 0], v1 = bufA[r * TS + c + 1];
        float v2 = bufA[r * TS + c + 2], v3 = bufA[r * TS + c + 3];
        float s = v0 + v1 + v2 + v3;
        float ss = v0 * v0 + v1 * v1 + v2 * v2 + v3 * v3;
        for (int o = 16; o; o >>= 1) {
            s  += __shfl_xor_sync(0xffffffffu, s,  o);
            ss += __shfl_xor_sync(0xffffffffu, ss, o);
        }
        float mu = s * (1.f / 128.f);
        float inv = rsqrtf(ss * (1.f / 128.f) - mu * mu + LN_EPS);
        size_t ob = (size_t)(row0 + r) * Dm;
        out[ob + c + 0] = (v0 - mu) * inv * g2[c + 0] + b2[c + 0];
        out[ob + c + 1] = (v1 - mu) * inv * g2[c + 1] + b2[c + 1];
        out[ob + c + 2] = (v2 - mu) * inv * g2[c + 2] + b2[c + 2];
        out[ob + c + 3] = (v3 - mu) * inv * g2[c + 3] + b2[c + 3];
    }
}

extern "C" void kernel_launch(void* const* d_in, const int* in_sizes, int n_in,
                              void* d_out, int out_size) {
    const float* tokens = (const float*)d_in[0];
    const float* Wq = (const float*)d_in[1];
    const float* Wk = (const float*)d_in[2];
    const float* Wv = (const float*)d_in[3];
    const float* Wg = (const float*)d_in[4];
    const float* bg = (const float*)d_in[5];
    const float* Wo = (const float*)d_in[6];
    const float* g1 = (const float*)d_in[7];
    const float* b1 = (const float*)d_in[8];
    const float* g2 = (const float*)d_in[9];
    const float* b2 = (const float*)d_in[10];
    float* out = (float*)d_out;

    size_t smA = (size_t)(3 * TILE * TS) * sizeof(float);           // 198144
    size_t smB = (size_t)(2 * TILE * TS) * sizeof(float);           // 132096
    size_t smD = (size_t)(3 * TILE * TS + 256) * sizeof(float);     // 199168

    cudaFuncSetAttribute(k_proj,   cudaFuncAttributeMaxDynamicSharedMemorySize, (int)smA);
    cudaFuncSetAttribute(k_chunkU, cudaFuncAttributeMaxDynamicSharedMemorySize, (int)smB);
    cudaFuncSetAttribute(k_attn,   cudaFuncAttributeMaxDynamicSharedMemorySize, (int)smD);

    k_proj<<<NCH, 256, smA>>>(tokens, Wq, Wk, Wv, Wg, bg, g1, b1);
    k_chunkU<<<NCH, 256, smB>>>();
    k_prefix<<<dim3(65, 2), 256>>>();
    k_attn<<<NCH, 256, smD>>>(tokens, Wo, g2, b2, out);
}

// round 2
// speedup vs baseline: 2.1554x; 2.1554x over previous
#include <cuda_runtime.h>
#include <math.h>

#define Dm 128
#define TS 132            // smem row stride (floats), 16B-aligned rows
#define NROWS 8192        // B*T
#define NCH 64            // chunks of 128 rows
#define CPB 32            // chunks per batch
#define LN_EPS 1e-5f
#define ATT_EPS 1e-6f
typedef unsigned long long ull;

// ---- scratch ----
__device__ float g_X  [NROWS * Dm];
__device__ float g_Qp [NROWS * Dm];
__device__ float g_KpT[NCH * Dm * Dm];   // per chunk: [h][row]
__device__ float g_V  [NROWS * Dm];
__device__ float g_G  [NROWS * Dm];
__device__ float g_Vg [NROWS * Dm];
__device__ float g_U  [NCH * Dm * Dm];
__device__ float g_uv [NCH * Dm];
__device__ float g_S  [NCH * Dm * Dm];
__device__ float g_sv [NCH * Dm];
__device__ float g_At [NROWS * Dm];

// ---- f32x2 helpers ----
__device__ __forceinline__ ull pack2(float lo, float hi) {
    ull r; asm("mov.b64 %0, {%1,%2};" : "=l"(r) : "f"(lo), "f"(hi)); return r;
}
__device__ __forceinline__ void ffma2(ull& d, ull a, ull b) {
    asm("fma.rn.f32x2 %0, %1, %2, %0;" : "+l"(d) : "l"(a), "l"(b));
}
__device__ __forceinline__ float2 unp2(ull v) {
    float2 r; asm("mov.b64 {%0,%1}, %2;" : "=f"(r.x), "=f"(r.y) : "l"(v)); return r;
}
__device__ __forceinline__ float phi_f(float x) { return x > 0.f ? x + 1.f : expf(x); }
__device__ __forceinline__ float sigmoid_f(float x) { return 1.f / (1.f + expf(-x)); }

// ---- tile loader: R rows x 128 cols, global row-major -> smem stride TS ----
template<int R>
__device__ __forceinline__ void ldtile(const float* __restrict__ g, float* __restrict__ s) {
    int tid = threadIdx.x;
    const float4* g4 = (const float4*)g;
#pragma unroll
    for (int i = 0; i < (R * 32) / 256; i++) {
        int idx = tid + i * 256;
        int r = idx >> 5, c = (idx & 31) * 4;
        float4 v = g4[idx];
        *(float4*)&s[r * TS + c] = v;
    }
}

// ---- 64x128x128 GEMM microkernel: acc += A[64xK] * B[Kx128], f32x2 packed ----
// thread: rows tr..tr+3, cols {tc..tc+3, tc+64..tc+67}; acc[i][p] pairs.
__device__ __forceinline__ void mm64(const float* __restrict__ A, const float* __restrict__ B,
                                     ull acc[4][4], int tr, int tc) {
#pragma unroll 2
    for (int k0 = 0; k0 < 128; k0 += 4) {
        float areg[4][4];  // [kk][i]
#pragma unroll
        for (int i = 0; i < 4; i++) {
            float4 av = *(const float4*)&A[(tr + i) * TS + k0];
            areg[0][i] = av.x; areg[1][i] = av.y; areg[2][i] = av.z; areg[3][i] = av.w;
        }
#pragma unroll
        for (int kk = 0; kk < 4; kk++) {
            const float* brow = &B[(k0 + kk) * TS + tc];
            float4 b0 = *(const float4*)brow;
            float4 b1 = *(const float4*)(brow + 64);
            ull bp0 = pack2(b0.x, b0.y), bp1 = pack2(b0.z, b0.w);
            ull bp2 = pack2(b1.x, b1.y), bp3 = pack2(b1.z, b1.w);
#pragma unroll
            for (int i = 0; i < 4; i++) {
                ull as = pack2(areg[kk][i], areg[kk][i]);
                ffma2(acc[i][0], as, bp0);
                ffma2(acc[i][1], as, bp1);
                ffma2(acc[i][2], as, bp2);
                ffma2(acc[i][3], as, bp3);
            }
        }
    }
}

__device__ __forceinline__ void acc_zero(ull acc[4][4]) {
#pragma unroll
    for (int i = 0; i < 4; i++)
#pragma unroll
        for (int p = 0; p < 4; p++) acc[i][p] = 0ull;
}

// unpack acc -> f[i][0..7]: cols tc+{0,1,2,3}, tc+64+{0,1,2,3}
__device__ __forceinline__ void acc_unpack(ull acc[4][4], float f[4][8]) {
#pragma unroll
    for (int i = 0; i < 4; i++) {
#pragma unroll
        for (int p = 0; p < 4; p++) {
            float2 v = unp2(acc[i][p]);
            f[i][p * 2] = v.x; f[i][p * 2 + 1] = v.y;
        }
    }
}

// ---- kernel: LN1 -> g_X ----
__global__ void __launch_bounds__(256) k_ln(const float* __restrict__ tokens,
                                            const float* __restrict__ g1,
                                            const float* __restrict__ b1) {
    int lane = threadIdx.x & 31, warp = threadIdx.x >> 5;
    int row = blockIdx.x * 8 + warp;
    float4 v = ((const float4*)(tokens + (size_t)row * Dm))[lane];
    float s = v.x + v.y + v.z + v.w;
    float ss = v.x * v.x + v.y * v.y + v.z * v.z + v.w * v.w;
#pragma unroll
    for (int o = 16; o; o >>= 1) {
        s  += __shfl_xor_sync(0xffffffffu, s,  o);
        ss += __shfl_xor_sync(0xffffffffu, ss, o);
    }
    float mu = s * (1.f / 128.f);
    float inv = rsqrtf(ss * (1.f / 128.f) - mu * mu + LN_EPS);
    int c = lane * 4;
    float4 gg = ((const float4*)g1)[lane], bb = ((const float4*)b1)[lane];
    float4 o4;
    o4.x = (v.x - mu) * inv * gg.x + bb.x;
    o4.y = (v.y - mu) * inv * gg.y + bb.y;
    o4.z = (v.z - mu) * inv * gg.z + bb.z;
    o4.w = (v.w - mu) * inv * gg.w + bb.w;
    *(float4*)&g_X[(size_t)row * Dm + c] = o4;
}

// ---- kernel: projections. grid 512 = ci*8 + half*4 + proj ----
__global__ void __launch_bounds__(256) k_proj(const float* __restrict__ Wq,
                                              const float* __restrict__ Wk,
                                              const float* __restrict__ Wv,
                                              const float* __restrict__ Wg) {
    extern __shared__ float sm[];
    float* xs = sm;               // 64*TS
    float* ws = sm + 64 * TS;     // 128*TS
    float* stage = sm + 192 * TS; // 128*65 (K transpose)
    int tid = threadIdx.x;
    int bi = blockIdx.x;
    int proj = bi & 3, half = (bi >> 2) & 1, ci = bi >> 3;
    int row0 = ci * Dm + half * 64;
    const float* W = proj == 0 ? Wq : proj == 1 ? Wk : proj == 2 ? Wv : Wg;
    ldtile<64>(g_X + (size_t)row0 * Dm, xs);
    ldtile<128>(W, ws);
    __syncthreads();
    int tr = (tid >> 4) * 4, tc = (tid & 15) * 4;
    ull acc[4][4]; acc_zero(acc);
    mm64(xs, ws, acc, tr, tc);
    float f[4][8]; acc_unpack(acc, f);

    if (proj <= 1) {
#pragma unroll
        for (int i = 0; i < 4; i++)
#pragma unroll
            for (int j = 0; j < 8; j++) f[i][j] = phi_f(f[i][j]);
    }
    if (proj == 1) {
        // transpose via smem stage -> g_KpT[ci][h][row]
#pragma unroll
        for (int i = 0; i < 4; i++) {
#pragma unroll
            for (int j = 0; j < 4; j++) {
                stage[(tc + j) * 65 + tr + i] = f[i][j];
                stage[(tc + 64 + j) * 65 + tr + i] = f[i][j + 4];
            }
        }
        __syncthreads();
        int lane = tid & 31, warp = tid >> 5;
        float* dst = g_KpT + (size_t)ci * (Dm * Dm) + half * 64;
#pragma unroll
        for (int q = 0; q < 16; q++) {
            int h = warp * 16 + q;
            dst[(size_t)h * Dm + lane]      = stage[h * 65 + lane];
            dst[(size_t)h * Dm + lane + 32] = stage[h * 65 + lane + 32];
        }
    } else {
        float* dst = proj == 0 ? g_Qp : proj == 2 ? g_V : g_G;
#pragma unroll
        for (int i = 0; i < 4; i++) {
            float4 lo = make_float4(f[i][0], f[i][1], f[i][2], f[i][3]);
            float4 hi = make_float4(f[i][4], f[i][5], f[i][6], f[i][7]);
            *(float4*)&dst[(size_t)(row0 + tr + i) * Dm + tc] = lo;
            *(float4*)&dst[(size_t)(row0 + tr + i) * Dm + tc + 64] = hi;
        }
    }
}

// ---- kernel: Vg = V * sigmoid(G + bg) ----
__global__ void __launch_bounds__(256) k_gate(const float* __restrict__ bg) {
    int idx = blockIdx.x * 256 + threadIdx.x;
    float4 v = ((const float4*)g_V)[idx];
    float4 g = ((const float4*)g_G)[idx];
    float4 b = ((const float4*)bg)[idx & 31];
    float4 o;
    o.x = v.x * sigmoid_f(g.x + b.x);
    o.y = v.y * sigmoid_f(g.y + b.y);
    o.z = v.z * sigmoid_f(g.z + b.z);
    o.w = v.w * sigmoid_f(g.w + b.w);
    ((float4*)g_Vg)[idx] = o;
}

// ---- kernel: per-chunk U = Kp^T Vg (via KpT row-major), u = rowsum(KpT) ----
__global__ void __launch_bounds__(256) k_chunkU() {
    extern __shared__ float sm[];
    float* as = sm;            // 64*TS
    float* bs = sm + 64 * TS;  // 128*TS
    int tid = threadIdx.x;
    int hh = blockIdx.x & 1, ci = blockIdx.x >> 1;
    ldtile<64>(g_KpT + (size_t)ci * (Dm * Dm) + hh * 64 * Dm, as);
    ldtile<128>(g_Vg + (size_t)ci * (Dm * Dm), bs);
    __syncthreads();
    int lane = tid & 31, warp = tid >> 5;
#pragma unroll
    for (int q = 0; q < 8; q++) {
        int r = warp * 8 + q;
        float s = as[r * TS + lane] + as[r * TS + lane + 32]
                + as[r * TS + lane + 64] + as[r * TS + lane + 96];
#pragma unroll
        for (int o = 16; o; o >>= 1) s += __shfl_xor_sync(0xffffffffu, s, o);
        if (lane == 0) g_uv[ci * Dm + hh * 64 + r] = s;
    }
    int tr = (tid >> 4) * 4, tc = (tid & 15) * 4;
    ull acc[4][4]; acc_zero(acc);
    mm64(as, bs, acc, tr, tc);
    float f[4][8]; acc_unpack(acc, f);
    float* dst = g_U + (size_t)ci * (Dm * Dm) + (size_t)(hh * 64) * Dm;
#pragma unroll
    for (int i = 0; i < 4; i++) {
        *(float4*)&dst[(size_t)(tr + i) * Dm + tc] = make_float4(f[i][0], f[i][1], f[i][2], f[i][3]);
        *(float4*)&dst[(size_t)(tr + i) * Dm + tc + 64] = make_float4(f[i][4], f[i][5], f[i][6], f[i][7]);
    }
}

// ---- kernel: exclusive prefix over chunks, prefetched ----
__global__ void k_prefix() {
    int b = blockIdx.y;
    int e = blockIdx.x * blockDim.x + threadIdx.x;
    if (e < Dm * Dm) {
        float acc = 0.f;
        float nxt = g_U[(size_t)(b * CPB) * (Dm * Dm) + e];
        for (int c = 0; c < CPB; c++) {
            size_t idx = (size_t)(b * CPB + c) * (Dm * Dm) + e;
            float cur = nxt;
            if (c < CPB - 1) nxt = g_U[idx + Dm * Dm];
            g_S[idx] = acc;
            acc += cur;
        }
    } else if (e < Dm * Dm + Dm) {
        int h = e - Dm * Dm;
        float acc = 0.f;
        float nxt = g_uv[(b * CPB) * Dm + h];
        for (int c = 0; c < CPB; c++) {
            int idx = (b * CPB + c) * Dm + h;
            float cur = nxt;
            if (c < CPB - 1) nxt = g_uv[idx + Dm];
            g_sv[idx] = acc;
            acc += cur;
        }
    }
}

// ---- kernel: A=QpKp^T mask, denom, intra+inter, attn -> g_At. grid 128 ----
__global__ void __launch_bounds__(256) k_attn1() {
    extern __shared__ float sm[];
    float* bufQ = sm;                 // 64*TS
    float* bufA = sm + 64 * TS;       // 64*TS
    float* bufB = sm + 128 * TS;      // 128*TS : KpT -> Vg
    float* bufC = sm + 256 * TS;      // 128*TS : S
    float* sprev = sm + 384 * TS;     // 128
    float* denom = sprev + 128;       // 64
    int tid = threadIdx.x;
    int rh = blockIdx.x & 1, ci = blockIdx.x >> 1;
    int row0 = ci * Dm + rh * 64;

    ldtile<64>(g_Qp + (size_t)row0 * Dm, bufQ);
    ldtile<128>(g_KpT + (size_t)ci * (Dm * Dm), bufB);
    ldtile<128>(g_S + (size_t)ci * (Dm * Dm), bufC);
    if (tid < 128) sprev[tid] = g_sv[ci * Dm + tid];
    __syncthreads();

    int tr = (tid >> 4) * 4, tc = (tid & 15) * 4;
    ull acc[4][4]; acc_zero(acc);
    mm64(bufQ, bufB, acc, tr, tc);          // A = Qp @ KpT^T(=Kp^T)
    float f[4][8]; acc_unpack(acc, f);
#pragma unroll
    for (int i = 0; i < 4; i++) {
        int qr = rh * 64 + tr + i;
#pragma unroll
        for (int j = 0; j < 4; j++) {
            if (tc + j > qr) f[i][j] = 0.f;
            if (tc + 64 + j > qr) f[i][j + 4] = 0.f;
        }
    }
#pragma unroll
    for (int i = 0; i < 4; i++) {
        *(float4*)&bufA[(tr + i) * TS + tc] = make_float4(f[i][0], f[i][1], f[i][2], f[i][3]);
        *(float4*)&bufA[(tr + i) * TS + tc + 64] = make_float4(f[i][4], f[i][5], f[i][6], f[i][7]);
    }
    __syncthreads();

    ldtile<128>(g_Vg + (size_t)ci * (Dm * Dm), bufB);   // overwrite KpT
    {
        int lane = tid & 31, warp = tid >> 5;
#pragma unroll
        for (int q = 0; q < 8; q++) {
            int r = warp * 8 + q;
            float s = 0.f;
#pragma unroll
            for (int c4 = 0; c4 < 4; c4++) {
                int c = lane + c4 * 32;
                s += bufA[r * TS + c] + bufQ[r * TS + c] * sprev[c];
            }
#pragma unroll
            for (int o = 16; o; o >>= 1) s += __shfl_xor_sync(0xffffffffu, s, o);
            if (lane == 0) denom[r] = fmaxf(s, ATT_EPS);
        }
    }
    __syncthreads();

    acc_zero(acc);
    mm64(bufA, bufB, acc, tr, tc);   // intra = A_mask @ Vg
    mm64(bufQ, bufC, acc, tr, tc);   // inter = Qp @ S
    acc_unpack(acc, f);
#pragma unroll
    for (int i = 0; i < 4; i++) {
        float inv = 1.f / denom[tr + i];
        float4 lo = make_float4(f[i][0] * inv, f[i][1] * inv, f[i][2] * inv, f[i][3] * inv);
        float4 hi = make_float4(f[i][4] * inv, f[i][5] * inv, f[i][6] * inv, f[i][7] * inv);
        *(float4*)&g_At[(size_t)(row0 + tr + i) * Dm + tc] = lo;
        *(float4*)&g_At[(size_t)(row0 + tr + i) * Dm + tc + 64] = hi;
    }
}

// ---- kernel: out = LN2(tokens + 0.1*attn@Wo). grid 128 ----
__global__ void __launch_bounds__(256) k_attn2(const float* __restrict__ tokens,
                                               const float* __restrict__ Wo,
                                               const float* __restrict__ g2,
                                               const float* __restrict__ b2,
                                               float* __restrict__ out) {
    extern __shared__ float sm[];
    float* bufA = sm;             // 64*TS : attn rows -> out_pre
    float* bufW = sm + 64 * TS;   // 128*TS
    int tid = threadIdx.x;
    int row0 = blockIdx.x * 64;
    ldtile<64>(g_At + (size_t)row0 * Dm, bufA);
    ldtile<128>(Wo, bufW);
    __syncthreads();
    int tr = (tid >> 4) * 4, tc = (tid & 15) * 4;
    ull acc[4][4]; acc_zero(acc);
    mm64(bufA, bufW, acc, tr, tc);
    float f[4][8]; acc_unpack(acc, f);
    __syncthreads();   // done reading bufA
#pragma unroll
    for (int i = 0; i < 4; i++) {
        const float* trow = tokens + (size_t)(row0 + tr + i) * Dm;
        float4 t0 = *(const float4*)&trow[tc];
        float4 t1 = *(const float4*)&trow[tc + 64];
        *(float4*)&bufA[(tr + i) * TS + tc] =
            make_float4(t0.x + 0.1f * f[i][0], t0.y + 0.1f * f[i][1],
                        t0.z + 0.1f * f[i][2], t0.w + 0.1f * f[i][3]);
        *(float4*)&bufA[(tr + i) * TS + tc + 64] =
            make_float4(t1.x + 0.1f * f[i][4], t1.y + 0.1f * f[i][5],
                        t1.z + 0.1f * f[i][6], t1.w + 0.1f * f[i][7]);
    }
    __syncthreads();
    int lane = tid & 31, warp = tid >> 5;
    float4 gg = ((const float4*)g2)[lane], bb = ((const float4*)b2)[lane];
#pragma unroll
    for (int q = 0; q < 8; q++) {
        int r = warp * 8 + q;
        float4 v = *(float4*)&bufA[r * TS + lane * 4];
        float s = v.x + v.y + v.z + v.w;
        float ss = v.x * v.x + v.y * v.y + v.z * v.z + v.w * v.w;
#pragma unroll
        for (int o = 16; o; o >>= 1) {
            s  += __shfl_xor_sync(0xffffffffu, s,  o);
            ss += __shfl_xor_sync(0xffffffffu, ss, o);
        }
        float mu = s * (1.f / 128.f);
        float inv = rsqrtf(ss * (1.f / 128.f) - mu * mu + LN_EPS);
        float4 o4;
        o4.x = (v.x - mu) * inv * gg.x + bb.x;
        o4.y = (v.y - mu) * inv * gg.y + bb.y;
        o4.z = (v.z - mu) * inv * gg.z + bb.z;
        o4.w = (v.w - mu) * inv * gg.w + bb.w;
        *(float4*)&out[(size_t)(row0 + r) * Dm + lane * 4] = o4;
    }
}

extern "C" void kernel_launch(void* const* d_in, const int* in_sizes, int n_in,
                              void* d_out, int out_size) {
    const float* tokens = (const float*)d_in[0];
    const float* Wq = (const float*)d_in[1];
    const float* Wk = (const float*)d_in[2];
    const float* Wv = (const float*)d_in[3];
    const float* Wg = (const float*)d_in[4];
    const float* bg = (const float*)d_in[5];
    const float* Wo = (const float*)d_in[6];
    const float* g1 = (const float*)d_in[7];
    const float* b1 = (const float*)d_in[8];
    const float* g2 = (const float*)d_in[9];
    const float* b2 = (const float*)d_in[10];
    float* out = (float*)d_out;

    size_t smP  = (size_t)(192 * TS + 128 * 65) * sizeof(float); // 134656
    size_t smU  = (size_t)(192 * TS) * sizeof(float);            // 101376
    size_t smA1 = (size_t)(384 * TS + 192) * sizeof(float);      // 203520
    size_t smA2 = (size_t)(192 * TS) * sizeof(float);            // 101376

    cudaFuncSetAttribute(k_proj,   cudaFuncAttributeMaxDynamicSharedMemorySize, (int)smP);
    cudaFuncSetAttribute(k_chunkU, cudaFuncAttributeMaxDynamicSharedMemorySize, (int)smU);
    cudaFuncSetAttribute(k_attn1,  cudaFuncAttributeMaxDynamicSharedMemorySize, (int)smA1);
    cudaFuncSetAttribute(k_attn2,  cudaFuncAttributeMaxDynamicSharedMemorySize, (int)smA2);

    k_ln<<<1024, 256>>>(tokens, g1, b1);
    k_proj<<<512, 256, smP>>>(Wq, Wk, Wv, Wg);
    k_gate<<<1024, 256>>>(bg);
    k_chunkU<<<128, 256, smU>>>();
    k_prefix<<<dim3(65, 2), 256>>>();
    k_attn1<<<128, 256, smA1>>>();
    k_attn2<<<128, 256, smA2>>>(tokens, Wo, g2, b2, out);
}